// round 12
// baseline (speedup 1.0000x reference)
#include <cuda_runtime.h>

#define B      128
#define IN     256
#define HS     512
#define OUT    256
#define SG     8                    // samples per CTA (one per warp)
#define GROUPN 256                  // CTAs (=arrivals) per sample

__device__ float        g_acc_da[B];   // zeroed at load; left zero by kernel
__device__ unsigned int g_cnt[B];
__device__ unsigned int g_done[B];

// ---------------------------------------------------------------------------
// Fused single-pass kernel. Warp = (sample b, rows i0=x and i1=x+256).
// Phase 1 reads hebb ONCE (__ldcs, kept in 32 regs across the spin), computes
// hactiv + da partials; after the per-sample spin, phase 3 writes hebb_new
// from registers (no second hebb read anywhere). Heads fused at the end.
// ---------------------------------------------------------------------------
__global__ __launch_bounds__(256, 3) void k_fused(
    const float* __restrict__ inputs, const float* __restrict__ hidden,
    const float* __restrict__ hebb,   const float* __restrict__ i2h_w,
    const float* __restrict__ i2h_b,  const float* __restrict__ w,
    const float* __restrict__ alpha,  const float* __restrict__ h2da_w,
    const float* __restrict__ h2da_b, const float* __restrict__ h2o_w,
    const float* __restrict__ h2o_b,  const float* __restrict__ h2v_w,
    const float* __restrict__ h2v_b,  float* __restrict__ hactiv,
    float* __restrict__ hebb_new,     float* __restrict__ activout,
    float* __restrict__ valueout)
{
    const int tid   = threadIdx.x;
    const int warp  = tid >> 5;
    const int lane  = tid & 31;
    const int i0    = blockIdx.x;          // row pair (i0, i0+256)
    const int i1    = i0 + 256;
    const int bbase = blockIdx.y * SG;
    const int b     = bbase + warp;

    __shared__ float4 shW0[HS / 4], shW1[HS / 4];   // 4 KB
    __shared__ float4 shA0[HS / 4], shA1[HS / 4];   // 4 KB
    __shared__ float4 shH[SG][HS / 4];              // 16 KB
    __shared__ float4 shI0[IN / 4], shI1[IN / 4];   // 2 KB

    // ---- preload ----
    {
        const float4* w0 = (const float4*)(w     + (size_t)i0 * HS);
        const float4* w1 = (const float4*)(w     + (size_t)i1 * HS);
        const float4* a0 = (const float4*)(alpha + (size_t)i0 * HS);
        const float4* a1 = (const float4*)(alpha + (size_t)i1 * HS);
        for (int t = tid; t < HS / 4; t += 256) {
            shW0[t] = w0[t]; shW1[t] = w1[t]; shA0[t] = a0[t]; shA1[t] = a1[t];
        }
        const float4* gh = (const float4*)(hidden + (size_t)bbase * HS);
        for (int t = tid; t < SG * HS / 4; t += 256) (&shH[0][0])[t] = gh[t];
        const float4* x0 = (const float4*)(i2h_w + (size_t)i0 * IN);
        const float4* x1 = (const float4*)(i2h_w + (size_t)i1 * IN);
        if (tid < IN / 4)           shI0[tid]          = x0[tid];
        else if (tid < IN / 2)      shI1[tid - IN / 4] = x1[tid - IN / 4];
    }
    __syncthreads();

    // ---- phase 1: hebb read (once) + hactiv ----
    const size_t r0off = ((size_t)b * HS + i0) * (HS / 4);
    const size_t r1off = ((size_t)b * HS + i1) * (HS / 4);
    const float4* hr0 = (const float4*)hebb + r0off;
    const float4* hr1 = (const float4*)hebb + r1off;

    float4 hb0[4], hb1[4];
#pragma unroll
    for (int k = 0; k < 4; ++k) {
        hb0[k] = __ldcs(hr0 + lane + 32 * k);
        hb1[k] = __ldcs(hr1 + lane + 32 * k);
    }

    float s0 = 0.f, s1 = 0.f;
#pragma unroll
    for (int k = 0; k < 4; ++k) {
        const float4 d  = shH[warp][lane + 32 * k];
        const float4 w0v = shW0[lane + 32 * k], a0v = shA0[lane + 32 * k];
        const float4 w1v = shW1[lane + 32 * k], a1v = shA1[lane + 32 * k];
        s0 = fmaf(fmaf(a0v.x, hb0[k].x, w0v.x), d.x, s0);
        s0 = fmaf(fmaf(a0v.y, hb0[k].y, w0v.y), d.y, s0);
        s0 = fmaf(fmaf(a0v.z, hb0[k].z, w0v.z), d.z, s0);
        s0 = fmaf(fmaf(a0v.w, hb0[k].w, w0v.w), d.w, s0);
        s1 = fmaf(fmaf(a1v.x, hb1[k].x, w1v.x), d.x, s1);
        s1 = fmaf(fmaf(a1v.y, hb1[k].y, w1v.y), d.y, s1);
        s1 = fmaf(fmaf(a1v.z, hb1[k].z, w1v.z), d.z, s1);
        s1 = fmaf(fmaf(a1v.w, hb1[k].w, w1v.w), d.w, s1);
    }
    {
        const float4* xin = (const float4*)(inputs + (size_t)b * IN);
#pragma unroll
        for (int k = 0; k < 2; ++k) {
            const float4 xv = __ldg(xin + lane + 32 * k);
            const float4 v0 = shI0[lane + 32 * k];
            const float4 v1 = shI1[lane + 32 * k];
            s0 = fmaf(v0.x, xv.x, s0); s0 = fmaf(v0.y, xv.y, s0);
            s0 = fmaf(v0.z, xv.z, s0); s0 = fmaf(v0.w, xv.w, s0);
            s1 = fmaf(v1.x, xv.x, s1); s1 = fmaf(v1.y, xv.y, s1);
            s1 = fmaf(v1.z, xv.z, s1); s1 = fmaf(v1.w, xv.w, s1);
        }
    }
#pragma unroll
    for (int off = 16; off; off >>= 1) {
        s0 += __shfl_xor_sync(0xffffffffu, s0, off);
        s1 += __shfl_xor_sync(0xffffffffu, s1, off);
    }

    float h0, h1, da;
    if (lane == 0) {
        h0 = tanhf(s0 + __ldg(i2h_b + i0));
        h1 = tanhf(s1 + __ldg(i2h_b + i1));
        hactiv[(size_t)b * HS + i0] = h0;
        hactiv[(size_t)b * HS + i1] = h1;
        const float part = __ldg(h2da_w + i0) * h0 + __ldg(h2da_w + i1) * h1;
        atomicAdd(&g_acc_da[b], part);
        __threadfence();
        atomicAdd(&g_cnt[b], 1u);
        // spin until all 256 row-CTAs of sample b arrived
        unsigned c;
        do {
            asm volatile("ld.acquire.gpu.u32 %0, [%1];" : "=r"(c) : "l"(g_cnt + b));
            if (c < GROUPN) __nanosleep(64);
        } while (c < GROUPN);
        da = tanhf(__ldcg(&g_acc_da[b]) + __ldg(h2da_b));
        // ORDER the acc read before the done signal — without this fence the
        // 256th arrival may reset g_acc_da while a slow warp's load is still
        // outstanding (this was the R11 hebb_new corruption).
        __threadfence();
        const unsigned old = atomicAdd(&g_done[b], 1u);
        if (old == GROUPN - 1) {        // last consumer: self-reset for replay
            g_acc_da[b] = 0.f;
            g_cnt[b]    = 0u;
            __threadfence();
            g_done[b]   = 0u;
        }
    }
    h0 = __shfl_sync(0xffffffffu, h0, 0);
    h1 = __shfl_sync(0xffffffffu, h1, 0);
    da = __shfl_sync(0xffffffffu, da, 0);

    // ---- phase 3: hebb update straight from registers ----
    const float c0 = da * h0, c1 = da * h1;
    float4* o0 = (float4*)hebb_new + r0off;
    float4* o1 = (float4*)hebb_new + r1off;
#pragma unroll
    for (int k = 0; k < 4; ++k) {
        const float4 d = shH[warp][lane + 32 * k];
        float4 r;
        r.x = fminf(1.f, fmaxf(-1.f, fmaf(c0, d.x, hb0[k].x)));
        r.y = fminf(1.f, fmaxf(-1.f, fmaf(c0, d.y, hb0[k].y)));
        r.z = fminf(1.f, fmaxf(-1.f, fmaf(c0, d.z, hb0[k].z)));
        r.w = fminf(1.f, fmaxf(-1.f, fmaf(c0, d.w, hb0[k].w)));
        __stcs(o0 + lane + 32 * k, r);
        r.x = fminf(1.f, fmaxf(-1.f, fmaf(c1, d.x, hb1[k].x)));
        r.y = fminf(1.f, fmaxf(-1.f, fmaf(c1, d.y, hb1[k].y)));
        r.z = fminf(1.f, fmaxf(-1.f, fmaf(c1, d.z, hb1[k].z)));
        r.w = fminf(1.f, fmaxf(-1.f, fmaf(c1, d.w, hb1[k].w)));
        __stcs(o1 + lane + 32 * k, r);
    }

    // ---- fused heads: this CTA computes output column o = blockIdx.x ------
    __syncthreads();                       // done with shW0 (phase-1 use)
    {
        const float4* ow = (const float4*)(h2o_w + (size_t)blockIdx.x * HS);
        for (int t = tid; t < HS / 4; t += 256) shW0[t] = ow[t];
    }
    __syncthreads();
    {
        const float4* ha = (const float4*)(hactiv + (size_t)b * HS);
        float s = 0.f, sv = 0.f;
#pragma unroll
        for (int k = 0; k < 4; ++k) {
            const float4 hv = ha[lane + 32 * k];
            const float4 wv = shW0[lane + 32 * k];
            s = fmaf(wv.x, hv.x, s); s = fmaf(wv.y, hv.y, s);
            s = fmaf(wv.z, hv.z, s); s = fmaf(wv.w, hv.w, s);
            if (blockIdx.x == 0) {
                const float4 v = __ldg((const float4*)h2v_w + lane + 32 * k);
                sv = fmaf(v.x, hv.x, sv); sv = fmaf(v.y, hv.y, sv);
                sv = fmaf(v.z, hv.z, sv); sv = fmaf(v.w, hv.w, sv);
            }
        }
#pragma unroll
        for (int off = 16; off; off >>= 1) {
            s += __shfl_xor_sync(0xffffffffu, s, off);
            if (blockIdx.x == 0) sv += __shfl_xor_sync(0xffffffffu, sv, off);
        }
        if (lane == 0) {
            activout[(size_t)b * OUT + blockIdx.x] = s + __ldg(h2o_b + blockIdx.x);
            if (blockIdx.x == 0) valueout[b] = sv + __ldg(h2v_b);
        }
    }
}

// ---------------------------------------------------------------------------
extern "C" void kernel_launch(void* const* d_in, const int* in_sizes, int n_in,
                              void* d_out, int out_size)
{
    const float* inputs = (const float*)d_in[0];
    const float* hidden = (const float*)d_in[1];
    const float* hebb   = (const float*)d_in[2];
    const float* i2h_w  = (const float*)d_in[3];
    const float* i2h_b  = (const float*)d_in[4];
    const float* w      = (const float*)d_in[5];
    const float* alpha  = (const float*)d_in[6];
    const float* h2o_w  = (const float*)d_in[7];
    const float* h2o_b  = (const float*)d_in[8];
    const float* h2v_w  = (const float*)d_in[9];
    const float* h2v_b  = (const float*)d_in[10];
    const float* h2da_w = (const float*)d_in[11];
    const float* h2da_b = (const float*)d_in[12];

    float* out      = (float*)d_out;
    float* activout = out;                                // [B, OUT]
    float* valueout = activout + (size_t)B * OUT;         // [B, 1]
    float* hactiv   = valueout + B;                       // [B, HS]
    float* hebb_new = hactiv + (size_t)B * HS;            // [B, HS, HS]

    k_fused<<<dim3(HS / 2, B / SG), 256>>>(
        inputs, hidden, hebb, i2h_w, i2h_b, w, alpha,
        h2da_w, h2da_b, h2o_w, h2o_b, h2v_w, h2v_b,
        hactiv, hebb_new, activout, valueout);
}

// round 13
// speedup vs baseline: 1.3907x; 1.3907x over previous
#include <cuda_runtime.h>

#define B      128
#define IN     256
#define HS     512
#define OUT    256
#define GROUPN 256u                 // arrivals per sample = 64 CTAs x 4 warps

__device__ float        g_acc_da[B];   // zeroed at load; left zero by kernel
__device__ unsigned int g_cnt[B];
__device__ unsigned int g_done[B];

// ---------------------------------------------------------------------------
// Single-pass fused kernel, 64-CTA sample groups.
// CTA = 2 samples x 4 warps; warp owns rows (i0, i0+1) of its sample and
// keeps their hebb in 32 registers from the single __ldcs read through the
// spin to the hebb_new write. Heads fused at the end (4 activout cols/CTA
// per sample). Counters self-reset for graph replay.
// ---------------------------------------------------------------------------
__global__ __launch_bounds__(256, 3) void k_fused(
    const float* __restrict__ inputs, const float* __restrict__ hidden,
    const float* __restrict__ hebb,   const float* __restrict__ i2h_w,
    const float* __restrict__ i2h_b,  const float* __restrict__ w,
    const float* __restrict__ alpha,  const float* __restrict__ h2da_w,
    const float* __restrict__ h2da_b, const float* __restrict__ h2o_w,
    const float* __restrict__ h2o_b,  const float* __restrict__ h2v_w,
    const float* __restrict__ h2v_b,  float* __restrict__ hactiv,
    float* __restrict__ hebb_new,     float* __restrict__ activout,
    float* __restrict__ valueout)
{
    const int tid  = threadIdx.x;
    const int warp = tid >> 5;
    const int lane = tid & 31;
    const int sl   = warp >> 2;            // sample slot in CTA (0,1)
    const int q    = warp & 3;             // row-pair slot (0..3)
    const int b    = blockIdx.y * 2 + sl;  // sample
    const int i0   = blockIdx.x * 8 + q * 2;
    const int i1   = i0 + 1;

    __shared__ float4 shW[8][HS / 4];      // 16 KB: CTA's 8 w-rows
    __shared__ float4 shA[8][HS / 4];      // 16 KB: CTA's 8 alpha-rows
    __shared__ float4 shH[2][HS / 4];      //  4 KB: 2 samples' hidden
    __shared__ float4 shX[2][IN / 4];      //  2 KB: 2 samples' inputs

    // ---- preload ----
    {
        const float4* gw = (const float4*)(w     + (size_t)blockIdx.x * 8 * HS);
        const float4* ga = (const float4*)(alpha + (size_t)blockIdx.x * 8 * HS);
        for (int t = tid; t < 8 * HS / 4; t += 256) {
            (&shW[0][0])[t] = gw[t];
            (&shA[0][0])[t] = ga[t];
        }
        const float4* gh = (const float4*)(hidden + (size_t)blockIdx.y * 2 * HS);
        if (tid < 2 * HS / 4) (&shH[0][0])[tid] = gh[tid];
        const float4* gx = (const float4*)(inputs + (size_t)blockIdx.y * 2 * IN);
        if (tid < 2 * IN / 4) (&shX[0][0])[tid] = gx[tid];
    }
    __syncthreads();

    // ---- phase 1: single hebb read (kept in regs) + hactiv ----
    const size_t r0off = ((size_t)b * HS + i0) * (HS / 4);
    const size_t r1off = ((size_t)b * HS + i1) * (HS / 4);
    const float4* hr0 = (const float4*)hebb + r0off;
    const float4* hr1 = (const float4*)hebb + r1off;

    float4 hb0[4], hb1[4];
#pragma unroll
    for (int k = 0; k < 4; ++k) {
        hb0[k] = __ldcs(hr0 + lane + 32 * k);
        hb1[k] = __ldcs(hr1 + lane + 32 * k);
    }

    float s0 = 0.f, s1 = 0.f;
    const int r0 = q * 2, r1 = q * 2 + 1;
#pragma unroll
    for (int k = 0; k < 4; ++k) {
        const float4 d   = shH[sl][lane + 32 * k];
        const float4 w0v = shW[r0][lane + 32 * k], a0v = shA[r0][lane + 32 * k];
        const float4 w1v = shW[r1][lane + 32 * k], a1v = shA[r1][lane + 32 * k];
        s0 = fmaf(fmaf(a0v.x, hb0[k].x, w0v.x), d.x, s0);
        s0 = fmaf(fmaf(a0v.y, hb0[k].y, w0v.y), d.y, s0);
        s0 = fmaf(fmaf(a0v.z, hb0[k].z, w0v.z), d.z, s0);
        s0 = fmaf(fmaf(a0v.w, hb0[k].w, w0v.w), d.w, s0);
        s1 = fmaf(fmaf(a1v.x, hb1[k].x, w1v.x), d.x, s1);
        s1 = fmaf(fmaf(a1v.y, hb1[k].y, w1v.y), d.y, s1);
        s1 = fmaf(fmaf(a1v.z, hb1[k].z, w1v.z), d.z, s1);
        s1 = fmaf(fmaf(a1v.w, hb1[k].w, w1v.w), d.w, s1);
    }
    {
        const float4* x0 = (const float4*)(i2h_w + (size_t)i0 * IN);
        const float4* x1 = (const float4*)(i2h_w + (size_t)i1 * IN);
#pragma unroll
        for (int k = 0; k < 2; ++k) {
            const float4 xv = shX[sl][lane + 32 * k];
            const float4 v0 = __ldg(x0 + lane + 32 * k);
            const float4 v1 = __ldg(x1 + lane + 32 * k);
            s0 = fmaf(v0.x, xv.x, s0); s0 = fmaf(v0.y, xv.y, s0);
            s0 = fmaf(v0.z, xv.z, s0); s0 = fmaf(v0.w, xv.w, s0);
            s1 = fmaf(v1.x, xv.x, s1); s1 = fmaf(v1.y, xv.y, s1);
            s1 = fmaf(v1.z, xv.z, s1); s1 = fmaf(v1.w, xv.w, s1);
        }
    }
#pragma unroll
    for (int off = 16; off; off >>= 1) {
        s0 += __shfl_xor_sync(0xffffffffu, s0, off);
        s1 += __shfl_xor_sync(0xffffffffu, s1, off);
    }

    float h0, h1, da;
    if (lane == 0) {
        h0 = tanhf(s0 + __ldg(i2h_b + i0));
        h1 = tanhf(s1 + __ldg(i2h_b + i1));
        hactiv[(size_t)b * HS + i0] = h0;
        hactiv[(size_t)b * HS + i1] = h1;
        const float part = __ldg(h2da_w + i0) * h0 + __ldg(h2da_w + i1) * h1;
        atomicAdd(&g_acc_da[b], part);
        __threadfence();
        atomicAdd(&g_cnt[b], 1u);
        // spin: sample group spans only 64 contiguous CTAs -> many groups
        // concurrently resident (this was the R12 serialization fix)
        unsigned c;
        do {
            asm volatile("ld.acquire.gpu.u32 %0, [%1];" : "=r"(c) : "l"(g_cnt + b));
            if (c < GROUPN) __nanosleep(64);
        } while (c < GROUPN);
        da = tanhf(__ldcg(&g_acc_da[b]) + __ldg(h2da_b));
        __threadfence();   // order the acc read before the done signal
        const unsigned old = atomicAdd(&g_done[b], 1u);
        if (old == GROUPN - 1) {        // last consumer: self-reset for replay
            g_acc_da[b] = 0.f;
            g_cnt[b]    = 0u;
            __threadfence();
            g_done[b]   = 0u;
        }
    }
    h0 = __shfl_sync(0xffffffffu, h0, 0);
    h1 = __shfl_sync(0xffffffffu, h1, 0);
    da = __shfl_sync(0xffffffffu, da, 0);

    // ---- phase 3: hebb update straight from registers ----
    const float c0 = da * h0, c1 = da * h1;
    float4* o0 = (float4*)hebb_new + r0off;
    float4* o1 = (float4*)hebb_new + r1off;
#pragma unroll
    for (int k = 0; k < 4; ++k) {
        const float4 d = shH[sl][lane + 32 * k];
        float4 r;
        r.x = fminf(1.f, fmaxf(-1.f, fmaf(c0, d.x, hb0[k].x)));
        r.y = fminf(1.f, fmaxf(-1.f, fmaf(c0, d.y, hb0[k].y)));
        r.z = fminf(1.f, fmaxf(-1.f, fmaf(c0, d.z, hb0[k].z)));
        r.w = fminf(1.f, fmaxf(-1.f, fmaf(c0, d.w, hb0[k].w)));
        __stcs(o0 + lane + 32 * k, r);
        r.x = fminf(1.f, fmaxf(-1.f, fmaf(c1, d.x, hb1[k].x)));
        r.y = fminf(1.f, fmaxf(-1.f, fmaf(c1, d.y, hb1[k].y)));
        r.z = fminf(1.f, fmaxf(-1.f, fmaf(c1, d.z, hb1[k].z)));
        r.w = fminf(1.f, fmaxf(-1.f, fmaf(c1, d.w, hb1[k].w)));
        __stcs(o1 + lane + 32 * k, r);
    }

    // ---- fused heads: warp computes activout col o for its sample ---------
    {
        const int o = blockIdx.x * 4 + q;           // covers [0, OUT)
        const float4* wrow = (const float4*)(h2o_w + (size_t)o * HS);
        const float4* ha   = (const float4*)(hactiv + (size_t)b * HS);
        float s = 0.f, sv = 0.f;
#pragma unroll
        for (int k = 0; k < 4; ++k) {
            const float4 hv = ha[lane + 32 * k];
            const float4 wv = __ldg(wrow + lane + 32 * k);
            s = fmaf(wv.x, hv.x, s); s = fmaf(wv.y, hv.y, s);
            s = fmaf(wv.z, hv.z, s); s = fmaf(wv.w, hv.w, s);
            if (blockIdx.x == 0 && q == 0) {
                const float4 v = __ldg((const float4*)h2v_w + lane + 32 * k);
                sv = fmaf(v.x, hv.x, sv); sv = fmaf(v.y, hv.y, sv);
                sv = fmaf(v.z, hv.z, sv); sv = fmaf(v.w, hv.w, sv);
            }
        }
#pragma unroll
        for (int off = 16; off; off >>= 1) {
            s += __shfl_xor_sync(0xffffffffu, s, off);
            if (blockIdx.x == 0 && q == 0) sv += __shfl_xor_sync(0xffffffffu, sv, off);
        }
        if (lane == 0) {
            activout[(size_t)b * OUT + o] = s + __ldg(h2o_b + o);
            if (blockIdx.x == 0 && q == 0) valueout[b] = sv + __ldg(h2v_b);
        }
    }
}

// ---------------------------------------------------------------------------
extern "C" void kernel_launch(void* const* d_in, const int* in_sizes, int n_in,
                              void* d_out, int out_size)
{
    const float* inputs = (const float*)d_in[0];
    const float* hidden = (const float*)d_in[1];
    const float* hebb   = (const float*)d_in[2];
    const float* i2h_w  = (const float*)d_in[3];
    const float* i2h_b  = (const float*)d_in[4];
    const float* w      = (const float*)d_in[5];
    const float* alpha  = (const float*)d_in[6];
    const float* h2o_w  = (const float*)d_in[7];
    const float* h2o_b  = (const float*)d_in[8];
    const float* h2v_w  = (const float*)d_in[9];
    const float* h2v_b  = (const float*)d_in[10];
    const float* h2da_w = (const float*)d_in[11];
    const float* h2da_b = (const float*)d_in[12];

    float* out      = (float*)d_out;
    float* activout = out;                                // [B, OUT]
    float* valueout = activout + (size_t)B * OUT;         // [B, 1]
    float* hactiv   = valueout + B;                       // [B, HS]
    float* hebb_new = hactiv + (size_t)B * HS;            // [B, HS, HS]

    k_fused<<<dim3(HS / 8, B / 2), 256>>>(
        inputs, hidden, hebb, i2h_w, i2h_b, w, alpha,
        h2da_w, h2da_b, h2o_w, h2o_b, h2v_w, h2v_b,
        hactiv, hebb_new, activout, valueout);
}

// round 14
// speedup vs baseline: 3.3680x; 2.4219x over previous
#include <cuda_runtime.h>

#define B      128
#define IN     256
#define HS     512
#define OUT    256
#define RG     8      // rows per CTA (one warp per row)
#define SG     8      // samples per CTA
#define NCTA_PER_SAMPLE (HS / RG)   // 64 arrivals per sample

__device__ float        g_acc_da[B];   // zeroed at load; left zero by kernel
__device__ unsigned int g_cnt[B];
__device__ unsigned int g_done[B];

// ---------------------------------------------------------------------------
// Two-pass fused kernel (R8 skeleton):
//  phase 1: hactiv, 4-sample unroll (16 hebb float4 in flight/warp),
//           dual accumulators per sample; w/alpha rows in SMEM.
//  spin:    64 arrivals per sample (proven non-serializing geometry).
//  phase 3: hebb re-read (L2-hot, __ldcs) + clipped update (__stcs).
//  heads:   fused activout/valueout.
// ---------------------------------------------------------------------------
__global__ __launch_bounds__(256, 2) void k_fused(
    const float* __restrict__ inputs, const float* __restrict__ hidden,
    const float* __restrict__ hebb,   const float* __restrict__ i2h_w,
    const float* __restrict__ i2h_b,  const float* __restrict__ w,
    const float* __restrict__ alpha,  const float* __restrict__ h2da_w,
    const float* __restrict__ h2da_b, const float* __restrict__ h2o_w,
    const float* __restrict__ h2o_b,  const float* __restrict__ h2v_w,
    const float* __restrict__ h2v_b,  float* __restrict__ hactiv,
    float* __restrict__ hebb_new,     float* __restrict__ activout,
    float* __restrict__ valueout)
{
    const int tid   = threadIdx.x;
    const int warp  = tid >> 5;
    const int lane  = tid & 31;
    const int i     = blockIdx.x * RG + warp;
    const int bbase = blockIdx.y * SG;

    __shared__ float4 shW[RG * HS / 4];    // 16 KB: this CTA's 8 w-rows
    __shared__ float4 shA[RG * HS / 4];    // 16 KB: this CTA's 8 alpha-rows
    __shared__ float4 shX[SG * IN / 4];    //  8 KB: 8 samples' inputs
    __shared__ float  sh_hact[SG * RG];
    __shared__ float  sh_wda[RG];
    __shared__ float  sh_da[SG];

    // preload weights + inputs
    {
        const float4* gw = (const float4*)(w     + (size_t)blockIdx.x * RG * HS);
        const float4* ga = (const float4*)(alpha + (size_t)blockIdx.x * RG * HS);
        for (int t = tid; t < RG * HS / 4; t += 256) { shW[t] = gw[t]; shA[t] = ga[t]; }
        const float4* gx = (const float4*)(inputs + (size_t)bbase * IN);
        for (int t = tid; t < SG * IN / 4; t += 256) shX[t] = gx[t];
        if (tid < RG) sh_wda[tid] = h2da_w[blockIdx.x * RG + tid];
    }

    float4 iw[2];
    {
        const float4* x4 = (const float4*)(i2h_w + (size_t)i * IN);
#pragma unroll
        for (int k = 0; k < 2; ++k) iw[k] = x4[lane + 32 * k];
    }
    const float bias = i2h_b[i];

    __syncthreads();

    // ---------------- phase 1: hactiv, 4 samples at a time ----------------
#pragma unroll
    for (int bb = 0; bb < SG; bb += 4) {
        const float4* hp0 = (const float4*)(hebb + ((size_t)(bbase + bb + 0) * HS + i) * HS);
        const float4* hp1 = (const float4*)(hebb + ((size_t)(bbase + bb + 1) * HS + i) * HS);
        const float4* hp2 = (const float4*)(hebb + ((size_t)(bbase + bb + 2) * HS + i) * HS);
        const float4* hp3 = (const float4*)(hebb + ((size_t)(bbase + bb + 3) * HS + i) * HS);
        const float4* q0  = (const float4*)(hidden + (size_t)(bbase + bb + 0) * HS);
        const float4* q1  = (const float4*)(hidden + (size_t)(bbase + bb + 1) * HS);
        const float4* q2  = (const float4*)(hidden + (size_t)(bbase + bb + 2) * HS);
        const float4* q3  = (const float4*)(hidden + (size_t)(bbase + bb + 3) * HS);

        // 16 hebb float4 loads issued together -> high MLP
        float4 A0[4], A1[4], A2[4], A3[4];
#pragma unroll
        for (int k = 0; k < 4; ++k) {
            A0[k] = hp0[lane + 32 * k];
            A1[k] = hp1[lane + 32 * k];
            A2[k] = hp2[lane + 32 * k];
            A3[k] = hp3[lane + 32 * k];
        }

        float sa0 = 0.f, sb0 = 0.f, sa1 = 0.f, sb1 = 0.f;
        float sa2 = 0.f, sb2 = 0.f, sa3 = 0.f, sb3 = 0.f;
#pragma unroll
        for (int k = 0; k < 4; ++k) {
            const float4 wv = shW[warp * (HS / 4) + lane + 32 * k];
            const float4 av = shA[warp * (HS / 4) + lane + 32 * k];
            const float4 d0 = __ldg(q0 + lane + 32 * k);
            const float4 d1 = __ldg(q1 + lane + 32 * k);
            const float4 d2 = __ldg(q2 + lane + 32 * k);
            const float4 d3 = __ldg(q3 + lane + 32 * k);
            sa0 = fmaf(fmaf(av.x, A0[k].x, wv.x), d0.x, sa0);
            sb0 = fmaf(fmaf(av.y, A0[k].y, wv.y), d0.y, sb0);
            sa0 = fmaf(fmaf(av.z, A0[k].z, wv.z), d0.z, sa0);
            sb0 = fmaf(fmaf(av.w, A0[k].w, wv.w), d0.w, sb0);
            sa1 = fmaf(fmaf(av.x, A1[k].x, wv.x), d1.x, sa1);
            sb1 = fmaf(fmaf(av.y, A1[k].y, wv.y), d1.y, sb1);
            sa1 = fmaf(fmaf(av.z, A1[k].z, wv.z), d1.z, sa1);
            sb1 = fmaf(fmaf(av.w, A1[k].w, wv.w), d1.w, sb1);
            sa2 = fmaf(fmaf(av.x, A2[k].x, wv.x), d2.x, sa2);
            sb2 = fmaf(fmaf(av.y, A2[k].y, wv.y), d2.y, sb2);
            sa2 = fmaf(fmaf(av.z, A2[k].z, wv.z), d2.z, sa2);
            sb2 = fmaf(fmaf(av.w, A2[k].w, wv.w), d2.w, sb2);
            sa3 = fmaf(fmaf(av.x, A3[k].x, wv.x), d3.x, sa3);
            sb3 = fmaf(fmaf(av.y, A3[k].y, wv.y), d3.y, sb3);
            sa3 = fmaf(fmaf(av.z, A3[k].z, wv.z), d3.z, sa3);
            sb3 = fmaf(fmaf(av.w, A3[k].w, wv.w), d3.w, sb3);
        }
#pragma unroll
        for (int k = 0; k < 2; ++k) {
            const float4 x0 = shX[(bb + 0) * (IN / 4) + lane + 32 * k];
            const float4 x1 = shX[(bb + 1) * (IN / 4) + lane + 32 * k];
            const float4 x2 = shX[(bb + 2) * (IN / 4) + lane + 32 * k];
            const float4 x3 = shX[(bb + 3) * (IN / 4) + lane + 32 * k];
            sa0 = fmaf(iw[k].x, x0.x, sa0); sb0 = fmaf(iw[k].y, x0.y, sb0);
            sa0 = fmaf(iw[k].z, x0.z, sa0); sb0 = fmaf(iw[k].w, x0.w, sb0);
            sa1 = fmaf(iw[k].x, x1.x, sa1); sb1 = fmaf(iw[k].y, x1.y, sb1);
            sa1 = fmaf(iw[k].z, x1.z, sa1); sb1 = fmaf(iw[k].w, x1.w, sb1);
            sa2 = fmaf(iw[k].x, x2.x, sa2); sb2 = fmaf(iw[k].y, x2.y, sb2);
            sa2 = fmaf(iw[k].z, x2.z, sa2); sb2 = fmaf(iw[k].w, x2.w, sb2);
            sa3 = fmaf(iw[k].x, x3.x, sa3); sb3 = fmaf(iw[k].y, x3.y, sb3);
            sa3 = fmaf(iw[k].z, x3.z, sa3); sb3 = fmaf(iw[k].w, x3.w, sb3);
        }
        float s0 = sa0 + sb0, s1 = sa1 + sb1, s2 = sa2 + sb2, s3 = sa3 + sb3;
#pragma unroll
        for (int off = 16; off; off >>= 1) {
            s0 += __shfl_xor_sync(0xffffffffu, s0, off);
            s1 += __shfl_xor_sync(0xffffffffu, s1, off);
            s2 += __shfl_xor_sync(0xffffffffu, s2, off);
            s3 += __shfl_xor_sync(0xffffffffu, s3, off);
        }
        if (lane == 0) {
            const float v0 = tanhf(s0 + bias);
            const float v1 = tanhf(s1 + bias);
            const float v2 = tanhf(s2 + bias);
            const float v3 = tanhf(s3 + bias);
            hactiv[(size_t)(bbase + bb + 0) * HS + i] = v0;
            hactiv[(size_t)(bbase + bb + 1) * HS + i] = v1;
            hactiv[(size_t)(bbase + bb + 2) * HS + i] = v2;
            hactiv[(size_t)(bbase + bb + 3) * HS + i] = v3;
            sh_hact[(bb + 0) * RG + warp] = v0;
            sh_hact[(bb + 1) * RG + warp] = v1;
            sh_hact[(bb + 2) * RG + warp] = v2;
            sh_hact[(bb + 3) * RG + warp] = v3;
        }
    }
    __syncthreads();

    // ---------------- da partials + counter (release) ----------------
    if (tid < SG) {
        const int b = bbase + tid;
        float sum = 0.f;
#pragma unroll
        for (int wv = 0; wv < RG; ++wv) sum += sh_wda[wv] * sh_hact[tid * RG + wv];
        atomicAdd(&g_acc_da[b], sum);
        __threadfence();
        atomicAdd(&g_cnt[b], 1u);
    }

    // ---------------- spin (acquire), consume, self-reset ----------------
    if (tid < SG) {
        const int b = bbase + tid;
        unsigned c;
        do {
            asm volatile("ld.acquire.gpu.u32 %0, [%1];" : "=r"(c) : "l"(g_cnt + b));
            if (c < NCTA_PER_SAMPLE) __nanosleep(64);
        } while (c < NCTA_PER_SAMPLE);
        sh_da[tid] = tanhf(__ldcg(&g_acc_da[b]) + h2da_b[0]);
        __threadfence();   // order acc read before done signal (R11 bug class)
        const unsigned old = atomicAdd(&g_done[b], 1u);
        if (old == NCTA_PER_SAMPLE - 1) {   // last consumer: reset for replay
            g_acc_da[b] = 0.f;
            g_cnt[b]    = 0u;
            __threadfence();
            g_done[b]   = 0u;
        }
    }
    __syncthreads();

    // ---------------- phase 3: hebb update (L2-hot re-read, reversed) -----
#pragma unroll 2
    for (int bb = SG - 1; bb >= 0; --bb) {
        const float coef = sh_da[bb] * sh_hact[bb * RG + warp];
        const size_t roff = ((size_t)(bbase + bb) * HS + i) * HS;
        const float4* hb = (const float4*)(hebb + roff);
        float4*       ob = (float4*)(hebb_new + roff);
        const float4* q  = (const float4*)(hidden + (size_t)(bbase + bb) * HS);
#pragma unroll
        for (int k = 0; k < 4; ++k) {
            const float4 h = __ldcs(hb + lane + 32 * k);
            const float4 x = __ldg(q + lane + 32 * k);
            float4 r;
            r.x = fminf(1.f, fmaxf(-1.f, fmaf(coef, x.x, h.x)));
            r.y = fminf(1.f, fmaxf(-1.f, fmaf(coef, x.y, h.y)));
            r.z = fminf(1.f, fmaxf(-1.f, fmaf(coef, x.z, h.z)));
            r.w = fminf(1.f, fmaxf(-1.f, fmaf(coef, x.w, h.w)));
            __stcs(ob + lane + 32 * k, r);
        }
    }

    // ---------------- fused heads (hactiv is L2-hot) ----------------------
    const int x = blockIdx.x;
    if (x < OUT / RG) {                         // x in [0,32): activout
        const int o = x * RG + warp;
        const float4* wrow = (const float4*)(h2o_w + (size_t)o * HS);
        float4 wv[4];
#pragma unroll
        for (int k = 0; k < 4; ++k) wv[k] = wrow[lane + 32 * k];
        const float obias = h2o_b[o];
#pragma unroll 2
        for (int bb = 0; bb < SG; ++bb) {
            const float4* ha = (const float4*)(hactiv + (size_t)(bbase + bb) * HS);
            float s = 0.f;
#pragma unroll
            for (int k = 0; k < 4; ++k) {
                const float4 h = ha[lane + 32 * k];
                s = fmaf(wv[k].x, h.x, s); s = fmaf(wv[k].y, h.y, s);
                s = fmaf(wv[k].z, h.z, s); s = fmaf(wv[k].w, h.w, s);
            }
#pragma unroll
            for (int off = 16; off; off >>= 1) s += __shfl_xor_sync(0xffffffffu, s, off);
            if (lane == 0) activout[(size_t)(bbase + bb) * OUT + o] = s + obias;
        }
    } else if (x == OUT / RG) {                 // x == 32: valueout
        const int b = bbase + warp;
        const float4* vw = (const float4*)h2v_w;
        const float4* ha = (const float4*)(hactiv + (size_t)b * HS);
        float s = 0.f;
#pragma unroll
        for (int k = 0; k < 4; ++k) {
            const float4 v = vw[lane + 32 * k];
            const float4 h = ha[lane + 32 * k];
            s = fmaf(v.x, h.x, s); s = fmaf(v.y, h.y, s);
            s = fmaf(v.z, h.z, s); s = fmaf(v.w, h.w, s);
        }
#pragma unroll
        for (int off = 16; off; off >>= 1) s += __shfl_xor_sync(0xffffffffu, s, off);
        if (lane == 0) valueout[b] = s + h2v_b[0];
    }
}

// ---------------------------------------------------------------------------
extern "C" void kernel_launch(void* const* d_in, const int* in_sizes, int n_in,
                              void* d_out, int out_size)
{
    const float* inputs = (const float*)d_in[0];
    const float* hidden = (const float*)d_in[1];
    const float* hebb   = (const float*)d_in[2];
    const float* i2h_w  = (const float*)d_in[3];
    const float* i2h_b  = (const float*)d_in[4];
    const float* w      = (const float*)d_in[5];
    const float* alpha  = (const float*)d_in[6];
    const float* h2o_w  = (const float*)d_in[7];
    const float* h2o_b  = (const float*)d_in[8];
    const float* h2v_w  = (const float*)d_in[9];
    const float* h2v_b  = (const float*)d_in[10];
    const float* h2da_w = (const float*)d_in[11];
    const float* h2da_b = (const float*)d_in[12];

    float* out      = (float*)d_out;
    float* activout = out;                                // [B, OUT]
    float* valueout = activout + (size_t)B * OUT;         // [B, 1]
    float* hactiv   = valueout + B;                       // [B, HS]
    float* hebb_new = hactiv + (size_t)B * HS;            // [B, HS, HS]

    k_fused<<<dim3(HS / RG, B / SG), 256>>>(
        inputs, hidden, hebb, i2h_w, i2h_b, w, alpha,
        h2da_w, h2da_b, h2o_w, h2o_b, h2v_w, h2v_b,
        hactiv, hebb_new, activout, valueout);
}